// round 4
// baseline (speedup 1.0000x reference)
#include <cuda_runtime.h>
#include <cuda_bf16.h>

// MaxPool3d kernel=2 stride=2 over [B=2, C=32, D=128, H=128, W=128] fp32.
// Output [2, 32, 64, 64, 64]. Pure HBM-streaming kernel: 512 MiB read +
// 64 MiB write, zero reuse -> optimize for DRAM efficiency only.
//
// R2 changes vs R1 (88.8us, DRAM=87%):
//  - __ldcs/__stcs evict-first streaming hints (no reuse, don't hold L2 state)
//  - __launch_bounds__(256, 8): cap regs at 32 -> 8 CTA/SM -> 64 warps/SM
//  - single base pointer + immediate offsets for all 8 loads (row=+512B,
//    slab=+64KiB, both in LDG 24-bit imm range) -> fewer regs, front-batched
//  - exact-fit grid, no bounds check

#define IN_W 128
#define IN_HW (128 * 128)
#define IN_DHW (128 * 128 * 128)
#define OUT_W 64
#define OUT_HW (64 * 64)
#define OUT_DHW (64 * 64 * 64)

__global__ __launch_bounds__(256, 8) void maxpool3d_k2s2_kernel(
    const float* __restrict__ in, float* __restrict__ out)
{
    int t = blockIdx.x * 256 + threadIdx.x;   // 0 .. 4,194,303 (exact fit)

    int w4 = t & 15;                 // quad index along out W (16 per row)
    int h  = (t >> 4) & 63;          // out h
    int d  = (t >> 10) & 63;         // out d
    int bc = t >> 16;                // plane (b*C + c), 0..63

    // Single base address; all other rows are compile-time immediate offsets.
    const float4* base = (const float4*)(in
        + (size_t)bc * IN_DHW
        + (size_t)(d << 1) * IN_HW
        + (size_t)(h << 1) * IN_W
        + (w4 << 3));

    // Offsets in float4 units: next h row = +IN_W/4 = 32, next d slab = +IN_HW/4 = 4096.
    // Front-batch all 8 independent 16B streaming loads (MLP=8 per thread).
    float4 a0 = __ldcs(base + 0);
    float4 a1 = __ldcs(base + 1);
    float4 b0 = __ldcs(base + 32);
    float4 b1 = __ldcs(base + 33);
    float4 c0 = __ldcs(base + 4096);
    float4 c1 = __ldcs(base + 4097);
    float4 e0 = __ldcs(base + 4128);
    float4 e1 = __ldcs(base + 4129);

    // Max across the 4 (d,h) rows.
    float4 m0, m1;
    m0.x = fmaxf(fmaxf(a0.x, b0.x), fmaxf(c0.x, e0.x));
    m0.y = fmaxf(fmaxf(a0.y, b0.y), fmaxf(c0.y, e0.y));
    m0.z = fmaxf(fmaxf(a0.z, b0.z), fmaxf(c0.z, e0.z));
    m0.w = fmaxf(fmaxf(a0.w, b0.w), fmaxf(c0.w, e0.w));
    m1.x = fmaxf(fmaxf(a1.x, b1.x), fmaxf(c1.x, e1.x));
    m1.y = fmaxf(fmaxf(a1.y, b1.y), fmaxf(c1.y, e1.y));
    m1.z = fmaxf(fmaxf(a1.z, b1.z), fmaxf(c1.z, e1.z));
    m1.w = fmaxf(fmaxf(a1.w, b1.w), fmaxf(c1.w, e1.w));

    // Pairwise max along W -> 4 outputs.
    float4 o;
    o.x = fmaxf(m0.x, m0.y);
    o.y = fmaxf(m0.z, m0.w);
    o.z = fmaxf(m1.x, m1.y);
    o.w = fmaxf(m1.z, m1.w);

    float4* op = (float4*)(out
        + (size_t)bc * OUT_DHW
        + (size_t)d * OUT_HW
        + (size_t)h * OUT_W
        + (w4 << 2));
    __stcs(op, o);
}

extern "C" void kernel_launch(void* const* d_in, const int* in_sizes, int n_in,
                              void* d_out, int out_size)
{
    const float* in = (const float*)d_in[0];
    float* out = (float*)d_out;

    // out_size = 16,777,216 -> 4,194,304 threads, exactly 16384 blocks of 256.
    int n_quads = out_size / 4;
    int blocks = n_quads / 256;
    maxpool3d_k2s2_kernel<<<blocks, 256>>>(in, out);
}